// round 14
// baseline (speedup 1.0000x reference)
#include <cuda_runtime.h>
#include <cstdint>

// Perception3D: 7-point stencil, 5 output groups per input channel.
// in : [B=4, C=16, D=64, H=64, W=64] fp32
// out: [B=4, C*G=80, D=64, H=64, W=64] fp32, out channel = c*5+g
//   g=0 ident, g=1 6-neighbor sum, g=2 gx, g=3 gy, g=4 gz (zero-padded shifts)
//
// R14: R6 config (256 thr, v8.f32 loads, st.global.wt v8 stores) with the
// CTA->work mapping transposed: bc comes from the LOW bits of blockIdx, so
// the concurrently-resident CTA wave spreads writes uniformly across all 64
// output volumes (full 335MB range) instead of clustering in a few.
// Single-variable test of DRAM bank/page concentration.

#define Dz 64
#define Hy 64
#define Wx 64
#define PLANE (Dz * Hy * Wx)
#define ROW   Wx
#define SLAB  (Hy * Wx)
#define W8    (Wx / 8)
#define G 5

__device__ __forceinline__ void ld8(const float* p, float* v) {
    asm("ld.global.nc.v8.f32 {%0,%1,%2,%3,%4,%5,%6,%7}, [%8];"
        : "=f"(v[0]), "=f"(v[1]), "=f"(v[2]), "=f"(v[3]),
          "=f"(v[4]), "=f"(v[5]), "=f"(v[6]), "=f"(v[7])
        : "l"(p));
}

__device__ __forceinline__ void ld8z(const float* p, float* v, bool ok) {
    if (ok) {
        ld8(p, v);
    } else {
#pragma unroll
        for (int i = 0; i < 8; i++) v[i] = 0.f;
    }
}

__device__ __forceinline__ void st8wt(float* p, const float* v) {
    asm volatile("st.global.wt.v8.f32 [%0], {%1,%2,%3,%4,%5,%6,%7,%8};"
        :: "l"(p),
           "f"(v[0]), "f"(v[1]), "f"(v[2]), "f"(v[3]),
           "f"(v[4]), "f"(v[5]), "f"(v[6]), "f"(v[7])
        : "memory");
}

__global__ void __launch_bounds__(256)
perception3d_kernel(const float* __restrict__ in, float* __restrict__ out) {
    // Block covers one (bc, d, h-half) tile: 256 threads = w8(8) x h-low(32).
    // blockIdx.x = hh + 2*d ... transposed: bc in LOW bits.
    unsigned bid = blockIdx.x;            // 0..8191
    unsigned bc  = bid & 63;              // LOW bits -> wave spreads over volumes
    unsigned d   = (bid >> 6) & (Dz - 1); // 0..63
    unsigned hh  = bid >> 12;             // 0..1 (h half)

    unsigned t  = threadIdx.x;
    unsigned w8 = t & (W8 - 1);           // 0..7
    unsigned h  = hh * 32 + (t >> 3);     // 0..63

    const float* base = in + (size_t)bc * PLANE + (size_t)d * SLAB + (size_t)h * ROW + (size_t)w8 * 8;

    float c[8], xp[8], xm[8], yp[8], ym[8];
    ld8(base, c);
    ld8z(base + SLAB, xp, d + 1 < Dz);
    ld8z(base - SLAB, xm, d >= 1);
    ld8z(base + ROW,  yp, h + 1 < Hy);
    ld8z(base - ROW,  ym, h >= 1);

    float nextv = (w8 + 1 < W8) ? __ldg(base + 8) : 0.f;
    float prevv = (w8 >= 1)     ? __ldg(base - 1) : 0.f;

    float zp[8], zm[8];
#pragma unroll
    for (int i = 0; i < 8; i++) {
        zp[i] = (i < 7) ? c[i + 1] : nextv;
        zm[i] = (i > 0) ? c[i - 1] : prevv;
    }

    float ns[8], gx[8], gy[8], gz[8];
#pragma unroll
    for (int i = 0; i < 8; i++) {
        ns[i] = xp[i] + xm[i] + yp[i] + ym[i] + zp[i] + zm[i];
        gx[i] = xp[i] - xm[i];
        gy[i] = yp[i] - ym[i];
        gz[i] = zp[i] - zm[i];
    }

    unsigned b  = bc >> 4;
    unsigned cc = bc & 15;
    size_t spatial = (size_t)d * SLAB + (size_t)h * ROW + (size_t)w8 * 8;
    float* ob = out + (size_t)b * (16 * G * PLANE) + (size_t)(cc * G) * PLANE + spatial;

    st8wt(ob,             c);
    st8wt(ob + 1 * PLANE, ns);
    st8wt(ob + 2 * PLANE, gx);
    st8wt(ob + 3 * PLANE, gy);
    st8wt(ob + 4 * PLANE, gz);
}

extern "C" void kernel_launch(void* const* d_in, const int* in_sizes, int n_in,
                              void* d_out, int out_size) {
    const float* in = (const float*)d_in[0];
    float* out = (float*)d_out;
    // 8192 blocks: bc(64) * d(64) * hh(2)
    perception3d_kernel<<<8192, 256>>>(in, out);
}

// round 15
// speedup vs baseline: 1.0406x; 1.0406x over previous
#include <cuda_runtime.h>
#include <cstdint>

// Perception3D: 7-point stencil, 5 output groups per input channel.
// in : [B=4, C=16, D=64, H=64, W=64] fp32
// out: [B=4, C*G=80, D=64, H=64, W=64] fp32, out channel = c*5+g
//   g=0 ident, g=1 6-neighbor sum, g=2 gx, g=3 gy, g=4 gz (zero-padded shifts)
//
// FINAL (R6 config, best of 14 rounds): fused single kernel, one thread = 8
// consecutive floats along W; v8.f32 256-bit loads (LDG.E.256) +
// st.global.wt v8 stores (STG.E.256). 256-thread blocks, 8192 CTAs,
// flat wave-scheduled grid, linear bid->(bc,d,h,w8) mapping.
//
// Roofline verdict: DRAM traffic == mandatory 335MB write footprint (input
// stays L2-resident across replays). Nine mechanisms isolated across 14
// rounds — float4/v8 width, 1/2-row shape, .cs/.wt/TMA-bulk store paths,
// 256/512 threads, store-order rotation, shuffle edge taps, group-split,
// persistent chunks, CTA-wave address spread — every deviation from this
// config was neutral or regressed. Pinned at ~5.75 TB/s DRAM-active (~72%
// of 8TB/s spec): the chip's pure-write HBM efficiency wall.
// Kernel 59.7-60.1us; bench 62.3-63.5us (replay noise).

#define Dz 64
#define Hy 64
#define Wx 64
#define PLANE (Dz * Hy * Wx)
#define ROW   Wx
#define SLAB  (Hy * Wx)
#define W8    (Wx / 8)
#define G 5

__device__ __forceinline__ void ld8(const float* p, float* v) {
    asm("ld.global.nc.v8.f32 {%0,%1,%2,%3,%4,%5,%6,%7}, [%8];"
        : "=f"(v[0]), "=f"(v[1]), "=f"(v[2]), "=f"(v[3]),
          "=f"(v[4]), "=f"(v[5]), "=f"(v[6]), "=f"(v[7])
        : "l"(p));
}

__device__ __forceinline__ void ld8z(const float* p, float* v, bool ok) {
    if (ok) {
        ld8(p, v);
    } else {
#pragma unroll
        for (int i = 0; i < 8; i++) v[i] = 0.f;
    }
}

__device__ __forceinline__ void st8wt(float* p, const float* v) {
    asm volatile("st.global.wt.v8.f32 [%0], {%1,%2,%3,%4,%5,%6,%7,%8};"
        :: "l"(p),
           "f"(v[0]), "f"(v[1]), "f"(v[2]), "f"(v[3]),
           "f"(v[4]), "f"(v[5]), "f"(v[6]), "f"(v[7])
        : "memory");
}

__global__ void __launch_bounds__(256)
perception3d_kernel(const float* __restrict__ in, float* __restrict__ out) {
    // tid over BC * D * H * W8 = 64*64*64*8 = 2,097,152
    unsigned tid = blockIdx.x * blockDim.x + threadIdx.x;

    unsigned w8 = tid & (W8 - 1);          // 0..7
    unsigned h  = (tid >> 3) & (Hy - 1);   // 0..63
    unsigned d  = (tid >> 9) & (Dz - 1);   // 0..63
    unsigned bc = tid >> 15;               // 0..63

    const float* base = in + (size_t)bc * PLANE + (size_t)d * SLAB + (size_t)h * ROW + (size_t)w8 * 8;

    float c[8], xp[8], xm[8], yp[8], ym[8];
    ld8(base, c);
    ld8z(base + SLAB, xp, d + 1 < Dz);
    ld8z(base - SLAB, xm, d >= 1);
    ld8z(base + ROW,  yp, h + 1 < Hy);
    ld8z(base - ROW,  ym, h >= 1);

    float nextv = (w8 + 1 < W8) ? __ldg(base + 8) : 0.f;
    float prevv = (w8 >= 1)     ? __ldg(base - 1) : 0.f;

    float zp[8], zm[8];
#pragma unroll
    for (int i = 0; i < 8; i++) {
        zp[i] = (i < 7) ? c[i + 1] : nextv;
        zm[i] = (i > 0) ? c[i - 1] : prevv;
    }

    float ns[8], gx[8], gy[8], gz[8];
#pragma unroll
    for (int i = 0; i < 8; i++) {
        ns[i] = xp[i] + xm[i] + yp[i] + ym[i] + zp[i] + zm[i];
        gx[i] = xp[i] - xm[i];
        gy[i] = yp[i] - ym[i];
        gz[i] = zp[i] - zm[i];
    }

    unsigned b  = bc >> 4;
    unsigned cc = bc & 15;
    size_t spatial = (size_t)d * SLAB + (size_t)h * ROW + (size_t)w8 * 8;
    float* ob = out + (size_t)b * (16 * G * PLANE) + (size_t)(cc * G) * PLANE + spatial;

    st8wt(ob,             c);
    st8wt(ob + 1 * PLANE, ns);
    st8wt(ob + 2 * PLANE, gx);
    st8wt(ob + 3 * PLANE, gy);
    st8wt(ob + 4 * PLANE, gz);
}

extern "C" void kernel_launch(void* const* d_in, const int* in_sizes, int n_in,
                              void* d_out, int out_size) {
    const float* in = (const float*)d_in[0];
    float* out = (float*)d_out;
    // 2,097,152 threads / 256 = 8192 blocks
    perception3d_kernel<<<8192, 256>>>(in, out);
}